// round 3
// baseline (speedup 1.0000x reference)
#include <cuda_runtime.h>

namespace {
constexpr int kB   = 64;
constexpr int kN   = 883;
constexpr int kT   = 12;
constexpr int kTN  = 16;
constexpr int kTOD = 288;
constexpr int kP   = kB * kN;              // 56512 (b,n) pairs, 2 per warp
constexpr unsigned FM = 0xffffffffu;

__device__ __forceinline__ float rsum16(float v) {
    v += __shfl_xor_sync(FM, v, 8, 16);
    v += __shfl_xor_sync(FM, v, 4, 16);
    v += __shfl_xor_sync(FM, v, 2, 16);
    v += __shfl_xor_sync(FM, v, 1, 16);
    return v;
}
__device__ __forceinline__ float rmax16(float v) {
    v = fmaxf(v, __shfl_xor_sync(FM, v, 8, 16));
    v = fmaxf(v, __shfl_xor_sync(FM, v, 4, 16));
    v = fmaxf(v, __shfl_xor_sync(FM, v, 2, 16));
    v = fmaxf(v, __shfl_xor_sync(FM, v, 1, 16));
    return v;
}
} // namespace

__global__ void __launch_bounds__(256) mode_att_kernel(
    const float* __restrict__ enc,
    const int*   __restrict__ xm,
    const float* __restrict__ dec,
    const float* __restrict__ kb,
    const float* __restrict__ vb,
    const float* __restrict__ aw,
    const float* __restrict__ ab,
    float*       __restrict__ out)
{
    // Per-warp staging: 4 tiles (KA,KB,VA,VB) x 192 floats = 768 floats.
    __shared__ float4 sm4[8][192];

    const int warp  = (blockIdx.x * blockDim.x + threadIdx.x) >> 5;
    const int wloc  = (threadIdx.x >> 5);
    const int lane  = threadIdx.x & 31;
    const int y     = lane & 15;
    const int h     = lane >> 4;               // which problem in this warp
    const int p     = warp * 2 + h;            // problem index (grid exactly covers kP)

    const int b = p / kN;
    const int n = p - b * kN;
    const int t = __ldg(xm + b * 2);           // x_mark_enc[b,0,0]

    // ---- coalesced tile load: each half-warp streams its 768B K and V tiles ----
    const size_t tile = ((size_t)(n * kTOD + t) * kTN) * kT;   // float offset
    const float4* __restrict__ kt = (const float4*)(kb + tile);
    const float4* __restrict__ vt = (const float4*)(vb + tile);
    float4* __restrict__ smw = &sm4[wloc][0];
#pragma unroll
    for (int j = 0; j < 3; ++j) {
        smw[h * 48 + j * 16 + y]       = kt[j * 16 + y];   // K tiles: f4[0..95]
        smw[96 + h * 48 + j * 16 + y]  = vt[j * 16 + y];   // V tiles: f4[96..191]
    }

    const float* __restrict__ qp = enc + (size_t)p * kT;
    float4 q0 = *(const float4*)(qp);
    float4 q1 = *(const float4*)(qp + 4);
    float4 q2 = *(const float4*)(qp + 8);

    __syncwarp();

    // ---- read back this lane's K row (conflict-free: 12-float row stride) ----
    const float* __restrict__ smf = (const float*)smw;
    const int krow = h * 192 + y * 12;
    float4 k0 = *(const float4*)(smf + krow);
    float4 k1 = *(const float4*)(smf + krow + 4);
    float4 k2 = *(const float4*)(smf + krow + 8);
    const int vrow = 384 + h * 192 + y * 12;
    float4 v0 = *(const float4*)(smf + vrow);
    float4 v1 = *(const float4*)(smf + vrow + 4);
    float4 v2 = *(const float4*)(smf + vrow + 8);

    // Per-key squared distance.
    float dd = 0.f, df;
    df = q0.x - k0.x; dd = fmaf(df, df, dd);
    df = q0.y - k0.y; dd = fmaf(df, df, dd);
    df = q0.z - k0.z; dd = fmaf(df, df, dd);
    df = q0.w - k0.w; dd = fmaf(df, df, dd);
    df = q1.x - k1.x; dd = fmaf(df, df, dd);
    df = q1.y - k1.y; dd = fmaf(df, df, dd);
    df = q1.z - k1.z; dd = fmaf(df, df, dd);
    df = q1.w - k1.w; dd = fmaf(df, df, dd);
    df = q2.x - k2.x; dd = fmaf(df, df, dd);
    df = q2.y - k2.y; dd = fmaf(df, df, dd);
    df = q2.z - k2.z; dd = fmaf(df, df, dd);
    df = q2.w - k2.w; dd = fmaf(df, df, dd);
    const float dist = sqrtf(dd);

    // --- first softmax over TN=16 keys ---
    const float s16  = rsum16(dist);
    const float mean = s16 * (1.0f / 16.0f);
    const float dv   = dist - mean;
    const float var  = rsum16(dv * dv) * (1.0f / 15.0f);
    const float istd = __fdividef(10.0f, sqrtf(var) + 1e-6f);
    const float sc   = (mean - dist) * istd;
    const float mx   = rmax16(sc);
    const float ex   = __expf(sc - mx);
    const float es   = rsum16(ex);
    const float prob = __fdividef(ex, es);

    // att_out partials: this lane's key prob times its V row.
    float o[12];
    o[0] = prob * v0.x; o[1]  = prob * v0.y; o[2]  = prob * v0.z; o[3]  = prob * v0.w;
    o[4] = prob * v1.x; o[5]  = prob * v1.y; o[6]  = prob * v1.z; o[7]  = prob * v1.w;
    o[8] = prob * v2.x; o[9]  = prob * v2.y; o[10] = prob * v2.z; o[11] = prob * v2.w;
#pragma unroll
    for (int m = 8; m >= 1; m >>= 1) {
#pragma unroll
        for (int d = 0; d < 12; ++d)
            o[d] += __shfl_xor_sync(FM, o[d], m, 16);
    }

    // --- second softmax over 17 keys (17th key = Q + 0.1, dist = sqrt(12*0.01)) ---
    const float d16    = 0.34641016151377545871f;
    const float mean17 = (s16 + d16) * (1.0f / 17.0f);
    const float dv2    = dist - mean17;
    const float c16    = d16  - mean17;
    const float var17  = (rsum16(dv2 * dv2) + c16 * c16) * (1.0f / 16.0f);
    const float istd2  = __fdividef(10.0f, sqrtf(var17) + 1e-6f);
    const float s2     = (mean17 - dist) * istd2;
    const float s2_16  = (mean17 - d16)  * istd2;
    const float mx2    = fmaxf(rmax16(s2), s2_16);
    const float e2     = __expf(s2    - mx2);
    const float e16    = __expf(s2_16 - mx2);
    const float inv    = __fdividef(1.0f, rsum16(e2) + e16);

    const float* __restrict__ awp = aw + n * (kTN + 1);
    float w = rsum16((e2 * inv) * __ldg(awp + y));
    w += (e16 * inv) * __ldg(awp + 16) + __ldg(ab + n);
    // butterfly leaves the full sum in every lane of the 16-group.

    // --- blend and write: lanes y=0,1,2 of each group write one float4 each ---
    if (y < 3) {
        const float omw = 1.0f - w;
        const size_t base = (size_t)p * kT + y * 4;
        float4 d4 = *(const float4*)(dec + base);
        const int j = y * 4;
        float4 r4 = make_float4(fmaf(omw, o[j + 0], w * d4.x),
                                fmaf(omw, o[j + 1], w * d4.y),
                                fmaf(omw, o[j + 2], w * d4.z),
                                fmaf(omw, o[j + 3], w * d4.w));
        *(float4*)(out + base) = r4;
    }
}

extern "C" void kernel_launch(void* const* d_in, const int* in_sizes, int n_in,
                              void* d_out, int out_size) {
    const float* enc = (const float*)d_in[0];
    const int*   xm  = (const int*)  d_in[1];
    const float* dec = (const float*)d_in[2];
    const float* kb  = (const float*)d_in[3];
    const float* vb  = (const float*)d_in[4];
    const float* aw  = (const float*)d_in[5];
    const float* ab  = (const float*)d_in[6];
    float*       out = (float*)d_out;

    const int problems_per_block = 16;                 // 8 warps * 2
    const int blocks = (kP + problems_per_block - 1) / problems_per_block;  // 3532
    mode_att_kernel<<<blocks, 256>>>(enc, xm, dec, kb, vb, aw, ab, out);
}

// round 4
// speedup vs baseline: 1.3322x; 1.3322x over previous
#include <cuda_runtime.h>

namespace {
constexpr int kB   = 64;
constexpr int kN   = 883;
constexpr int kT   = 12;
constexpr int kTN  = 16;
constexpr int kTOD = 288;
constexpr int kP   = kB * kN;              // 56512 (b,n) pairs, 2 per warp
constexpr unsigned FM = 0xffffffffu;
} // namespace

__global__ void __launch_bounds__(256) mode_att_kernel(
    const float* __restrict__ enc,
    const int*   __restrict__ xm,
    const float* __restrict__ dec,
    const float* __restrict__ kb,
    const float* __restrict__ vb,
    const float* __restrict__ aw,
    const float* __restrict__ ab,
    float*       __restrict__ out)
{
    const int warp = (blockIdx.x * blockDim.x + threadIdx.x) >> 5;
    const int lane = threadIdx.x & 31;
    const int y    = lane & 15;
    const int p    = warp * 2 + (lane >> 4);   // problem for this half-warp

    const int b = p / kN;
    const int n = p - b * kN;
    const int t = __ldg(xm + b * 2);           // x_mark_enc[b,0,0]

    const size_t rbase = ((size_t)((n * kTOD + t) * kTN + y)) * kT;
    const float* __restrict__ kr = kb + rbase;
    const float* __restrict__ vr = vb + rbase;

    // Front-batched loads for MLP.
    float4 k0 = *(const float4*)(kr);
    float4 k1 = *(const float4*)(kr + 4);
    float4 k2 = *(const float4*)(kr + 8);
    float4 v0 = *(const float4*)(vr);
    float4 v1 = *(const float4*)(vr + 4);
    float4 v2 = *(const float4*)(vr + 8);

    const float* __restrict__ qp = enc + (size_t)p * kT;
    float4 q0 = *(const float4*)(qp);
    float4 q1 = *(const float4*)(qp + 4);
    float4 q2 = *(const float4*)(qp + 8);

    const float* __restrict__ awp = aw + n * (kTN + 1);
    const float aw_y  = __ldg(awp + y);
    const float aw_16 = __ldg(awp + 16);
    const float bias  = __ldg(ab + n);

    // Per-key squared distance.
    float dd = 0.f, df;
    df = q0.x - k0.x; dd = fmaf(df, df, dd);
    df = q0.y - k0.y; dd = fmaf(df, df, dd);
    df = q0.z - k0.z; dd = fmaf(df, df, dd);
    df = q0.w - k0.w; dd = fmaf(df, df, dd);
    df = q1.x - k1.x; dd = fmaf(df, df, dd);
    df = q1.y - k1.y; dd = fmaf(df, df, dd);
    df = q1.z - k1.z; dd = fmaf(df, df, dd);
    df = q1.w - k1.w; dd = fmaf(df, df, dd);
    df = q2.x - k2.x; dd = fmaf(df, df, dd);
    df = q2.y - k2.y; dd = fmaf(df, df, dd);
    df = q2.z - k2.z; dd = fmaf(df, df, dd);
    df = q2.w - k2.w; dd = fmaf(df, df, dd);
    const float dist = sqrtf(dd);

    // ---- reduction wave 1: Sum(d) and Sum(d^2), interleaved ----
    float s1 = dist, s2 = dd;
#pragma unroll
    for (int m = 8; m >= 1; m >>= 1) {
        s1 += __shfl_xor_sync(FM, s1, m, 16);
        s2 += __shfl_xor_sync(FM, s2, m, 16);
    }

    // First softmax stats (raw moments, ddof=1).
    const float mean = s1 * (1.0f / 16.0f);
    const float var  = fmaxf((s2 - s1 * mean) * (1.0f / 15.0f), 0.0f);
    const float istd = __fdividef(10.0f, sqrtf(var) + 1e-6f);
    const float ex   = __expf((mean - dist) * istd);     // no max-sub: |score|<=37.5

    // Second softmax stats over 17 keys (17th = Q+0.1, dist = sqrt(12*0.01)).
    const float d16    = 0.34641016151377545871f;
    const float s1b    = s1 + d16;
    const float mean17 = s1b * (1.0f / 17.0f);
    const float var17  = fmaxf((s2 + d16 * d16 - s1b * mean17) * (1.0f / 16.0f), 0.0f);
    const float istd2  = __fdividef(10.0f, sqrtf(var17) + 1e-6f);
    const float e2     = __expf((mean17 - dist) * istd2);
    const float e16    = __expf((mean17 - d16)  * istd2);

    // ---- reduction wave 2: {Sum ex, Sum e2, Sum e2*aw, Sum ex*V[0..11]} ----
    float es = ex, es2 = e2, ea = e2 * aw_y;
    float o[12];
    o[0] = ex * v0.x; o[1]  = ex * v0.y; o[2]  = ex * v0.z; o[3]  = ex * v0.w;
    o[4] = ex * v1.x; o[5]  = ex * v1.y; o[6]  = ex * v1.z; o[7]  = ex * v1.w;
    o[8] = ex * v2.x; o[9]  = ex * v2.y; o[10] = ex * v2.z; o[11] = ex * v2.w;
#pragma unroll
    for (int m = 8; m >= 1; m >>= 1) {
        es  += __shfl_xor_sync(FM, es,  m, 16);
        es2 += __shfl_xor_sync(FM, es2, m, 16);
        ea  += __shfl_xor_sync(FM, ea,  m, 16);
#pragma unroll
        for (int d = 0; d < 12; ++d)
            o[d] += __shfl_xor_sync(FM, o[d], m, 16);
    }

    // Gate weight.
    const float inv2 = __fdividef(1.0f, es2 + e16);
    const float w    = (ea + e16 * aw_16) * inv2 + bias;
    const float omw  = (1.0f - w) * __fdividef(1.0f, es);   // fold prob norm into blend

    // ---- blend and write: lanes y=0,1,2 write one float4 each ----
    if (y < 3) {
        const size_t base = (size_t)p * kT + y * 4;
        float4 d4 = *(const float4*)(dec + base);
        const int j = y * 4;
        float4 r4 = make_float4(fmaf(omw, o[j + 0], w * d4.x),
                                fmaf(omw, o[j + 1], w * d4.y),
                                fmaf(omw, o[j + 2], w * d4.z),
                                fmaf(omw, o[j + 3], w * d4.w));
        *(float4*)(out + base) = r4;
    }
}

extern "C" void kernel_launch(void* const* d_in, const int* in_sizes, int n_in,
                              void* d_out, int out_size) {
    const float* enc = (const float*)d_in[0];
    const int*   xm  = (const int*)  d_in[1];
    const float* dec = (const float*)d_in[2];
    const float* kb  = (const float*)d_in[3];
    const float* vb  = (const float*)d_in[4];
    const float* aw  = (const float*)d_in[5];
    const float* ab  = (const float*)d_in[6];
    float*       out = (float*)d_out;

    const int problems_per_block = 16;                 // 8 warps * 2
    const int blocks = kP / problems_per_block;        // 3532 (exact)
    mode_att_kernel<<<blocks, 256>>>(enc, xm, dec, kb, vb, aw, ab, out);
}